// round 1
// baseline (speedup 1.0000x reference)
#include <cuda_runtime.h>
#include <math.h>

#define IMG   512
#define PADW  514
#define NVIEW 360
#define NBATCH 2

// Padded, duplicated, batch-interleaved image:
// g_pad[py*PADW+px] = ( b0[py-1][px-1], b0[py-1][px], b1[py-1][px-1], b1[py-1][px] )
// with zeros outside [0,512). One float4 load = one bilinear tap-row for BOTH batches.
__device__ float4 g_pad[PADW * PADW];
__device__ float2 g_cs[NVIEW];

__global__ void prep_cs_kernel() {
    int v = blockIdx.x * blockDim.x + threadIdx.x;
    if (v < NVIEW) {
        double a = -M_PI * (double)(v + 1) / (double)NVIEW - M_PI;
        g_cs[v] = make_float2((float)cos(a), (float)sin(a));
    }
}

__global__ void prep_img_kernel(const float* __restrict__ x) {
    int idx = blockIdx.x * blockDim.x + threadIdx.x;
    if (idx >= PADW * PADW) return;
    int py = idx / PADW;
    int px = idx - py * PADW;
    int y  = py - 1;
    int xx = px - 1;
    float4 f = make_float4(0.f, 0.f, 0.f, 0.f);
    if (y >= 0 && y < IMG) {
        const float* b0 = x;
        const float* b1 = x + IMG * IMG;
        if (xx >= 0 && xx < IMG) {
            f.x = b0[y * IMG + xx];
            f.z = b1[y * IMG + xx];
        }
        int x1 = xx + 1;
        if (x1 >= 0 && x1 < IMG) {
            f.y = b0[y * IMG + x1];
            f.w = b1[y * IMG + x1];
        }
    }
    g_pad[idx] = f;
}

__global__ __launch_bounds__(256) void fp_main_kernel(float* __restrict__ out) {
    int w = blockIdx.x * blockDim.x + threadIdx.x;   // detector bin 0..511
    int v = blockIdx.y;                              // view 0..359

    float2 cs = g_cs[v];
    float c = cs.x, s = cs.y;

    float wr  = (float)w - 255.5f;
    float bix = fmaf(c, wr, 255.5f);   // ix at hr=0
    float biy = fmaf(s, wr, 255.5f);   // iy at hr=0

    float acc0 = 0.f, acc1 = 0.f;

    #pragma unroll 4
    for (int h = 0; h < IMG; h++) {
        float hr = (float)h - 255.5f;
        float ix = fmaf(-s, hr, bix);
        float iy = fmaf( c, hr, biy);

        // All-taps-zero outside this open box; inside, the padded layout makes
        // every tap-row a single safe float4 load (zeros-padding is baked in).
        if (ix > -1.0f && ix < 512.0f && iy > -1.0f && iy < 512.0f) {
            float x0f = floorf(ix);
            float y0f = floorf(iy);
            float wx1 = ix - x0f;
            float wy1 = iy - y0f;
            float wx0 = 1.0f - wx1;
            float wy0 = 1.0f - wy1;

            int px = (int)x0f + 1;     // padded col of x0, in [0,512]
            int py = (int)y0f + 1;     // padded row of y0, in [0,512]

            const float4* p = g_pad + (py * PADW + px);
            float4 r0 = p[0];          // row y0: (b0[x0], b0[x1], b1[x0], b1[x1])
            float4 r1 = p[PADW];       // row y1

            float t0 = fmaf(wx0, r0.x, wx1 * r0.y);   // batch0 row y0
            float u0 = fmaf(wx0, r1.x, wx1 * r1.y);   // batch0 row y1
            float t1 = fmaf(wx0, r0.z, wx1 * r0.w);   // batch1 row y0
            float u1 = fmaf(wx0, r1.z, wx1 * r1.w);   // batch1 row y1

            acc0 = fmaf(wy0, t0, acc0);
            acc0 = fmaf(wy1, u0, acc0);
            acc1 = fmaf(wy0, t1, acc1);
            acc1 = fmaf(wy1, u1, acc1);
        }
    }

    // out shape (B,1,IMG,NVIEW): out[b*IMG*NVIEW + w*NVIEW + v]
    out[w * NVIEW + v]                 = acc0 * 0.5f;
    out[IMG * NVIEW + w * NVIEW + v]   = acc1 * 0.5f;
}

extern "C" void kernel_launch(void* const* d_in, const int* in_sizes, int n_in,
                              void* d_out, int out_size) {
    const float* x = (const float*)d_in[0];
    float* out = (float*)d_out;

    prep_cs_kernel<<<2, 256>>>();

    int npix = PADW * PADW;
    prep_img_kernel<<<(npix + 255) / 256, 256>>>(x);

    dim3 grid(IMG / 256, NVIEW);   // (2, 360)
    fp_main_kernel<<<grid, 256>>>(out);
}

// round 3
// speedup vs baseline: 1.0851x; 1.0851x over previous
#include <cuda_runtime.h>
#include <math.h>

#define IMG    512
#define PADW   514
#define NVIEW  360

// Padded, batch-interleaved image, two orientations (zeros baked into border):
//   g_rowimg[py*PADW+px] = (b0[py-1][px-1], b1[py-1][px-1])   row-major   [y][x]
//   g_colimg[px*PADW+py] = same value                          transposed  [x][y]
__device__ float2 g_rowimg[PADW * PADW];
__device__ float2 g_colimg[PADW * PADW];
// Per-view params: (a, bcoef, sA, sB); P = a*hr + (sA*wr + 255.5), Q = bcoef*hr + (sB*wr + 255.5)
__device__ float4 g_vp[NVIEW];
__device__ int    g_vmode[NVIEW];   // 0: iterate image rows (g_rowimg), 1: iterate cols (g_colimg)

__global__ void prep_kernel(const float* __restrict__ x) {
    int idx = blockIdx.x * blockDim.x + threadIdx.x;

    if (idx < NVIEW) {
        double ang = -M_PI * (double)(idx + 1) / (double)NVIEW - M_PI;
        float c = (float)cos(ang);
        float s = (float)sin(ang);
        // ix = c*wr - s*hr + 255.5 ; iy = s*wr + c*hr + 255.5
        if (fabsf(c) >= fabsf(s)) {          // row mode: stepped coord P = iy
            g_vp[idx] = make_float4(c, -s, s, c);
            g_vmode[idx] = 0;
        } else {                             // col mode: stepped coord P = ix
            g_vp[idx] = make_float4(-s, c, c, s);
            g_vmode[idx] = 1;
        }
    }

    if (idx < PADW * PADW) {
        int py = idx / PADW;
        int px = idx - py * PADW;
        int y = py - 1, xx = px - 1;
        float2 f = make_float2(0.f, 0.f);
        if (y >= 0 && y < IMG && xx >= 0 && xx < IMG) {
            f.x = x[y * IMG + xx];
            f.y = x[IMG * IMG + y * IMG + xx];
        }
        g_rowimg[py * PADW + px] = f;
        g_colimg[px * PADW + py] = f;
    }
}

__global__ __launch_bounds__(512) void fp_kernel(float* __restrict__ out) {
    __shared__ float2 srow[2][PADW];

    int v = blockIdx.x;           // view
    int w = threadIdx.x;          // detector bin 0..511

    float4 vp = g_vp[v];
    const float2* __restrict__ G = g_vmode[v] ? g_colimg : g_rowimg;

    float a  = vp.x;
    float bc = vp.y;
    float wr = (float)w - 255.5f;
    float A  = fmaf(vp.z, wr, 255.5f);   // P at hr=0
    float B  = fmaf(vp.w, wr, 255.5f);   // Q at hr=0
    float inv_a = 1.0f / a;              // |a| >= 0.7071

    float acc0 = 0.f, acc1 = 0.f;

    // preload image row 0 (padded row index 1)
    {
        const float2* src = G + (size_t)1 * PADW;
        srow[0][w] = src[w];
        if (w < 2) srow[0][512 + w] = src[512 + w];
    }

    for (int r = 0; r < IMG; r++) {
        __syncthreads();
        if (r + 1 < IMG) {
            const float2* src = G + (size_t)(r + 2) * PADW;
            int nb = (r + 1) & 1;
            srow[nb][w] = src[w];
            if (w < 2) srow[nb][512 + w] = src[512 + w];
        }
        const float2* row = srow[r & 1];

        float rf = (float)r;
        // h solving P(h)=r is hc = (r-A)/a + 255.5 (h-index space).
        // Support |P-r|<1 spans < 2*sqrt(2); 3 candidates from ceil(hc-1.4146) cover it.
        float hc = fmaf(rf - A, inv_a, 255.5f);
        float hb = ceilf(hc - 1.4146f);

        float hf = hb;
        float hr0 = hb - 255.5f;
        float P = fmaf(a, hr0, A);
        float Q = fmaf(bc, hr0, B);

        #pragma unroll
        for (int k = 0; k < 3; k++) {
            float wp = 1.0f - fabsf(P - rf);
            bool ok = (hf >= 0.0f) & (hf <= 511.0f) & (wp > 0.0f)
                    & (Q >= -1.0f) & (Q < 512.0f);
            if (ok) {
                float q0 = floorf(Q);
                float wq = Q - q0;
                int   px = (int)q0 + 1;
                float2 t0 = row[px];
                float2 t1 = row[px + 1];
                acc0 = fmaf(wp, fmaf(wq, t1.x - t0.x, t0.x), acc0);
                acc1 = fmaf(wp, fmaf(wq, t1.y - t0.y, t0.y), acc1);
            }
            hf += 1.0f;
            P  += a;
            Q  += bc;
        }
    }

    // out shape (B,1,IMG,NVIEW)
    out[w * NVIEW + v]               = acc0 * 0.5f;
    out[IMG * NVIEW + w * NVIEW + v] = acc1 * 0.5f;
}

extern "C" void kernel_launch(void* const* d_in, const int* in_sizes, int n_in,
                              void* d_out, int out_size) {
    const float* x = (const float*)d_in[0];
    float* out = (float*)d_out;

    int npix = PADW * PADW;
    prep_kernel<<<(npix + 255) / 256, 256>>>(x);

    fp_kernel<<<NVIEW, 512>>>(out);
}

// round 4
// speedup vs baseline: 1.4293x; 1.3172x over previous
#include <cuda_runtime.h>
#include <math.h>

#define IMG     512
#define PADW    514
#define NVIEW   360
#define NQ      4            // row-quarters per view
#define RQ      (IMG / NQ)   // 128 rows per CTA
#define OUTN    (2 * IMG * NVIEW)

// Padded, batch-interleaved image, two orientations (zeros baked into border).
__device__ float2 g_rowimg[PADW * PADW];
__device__ float2 g_colimg[PADW * PADW];
// Per-view params: (a, bcoef, sA, sB); P = a*hr + (sA*wr + 255.5), Q = bcoef*hr + (sB*wr + 255.5)
__device__ float4 g_vp[NVIEW];
__device__ int    g_vmode[NVIEW];
__device__ float  g_part[NQ][OUTN];   // per-quarter partial sinograms

__global__ void prep_kernel(const float* __restrict__ x) {
    int idx = blockIdx.x * blockDim.x + threadIdx.x;

    if (idx < NVIEW) {
        double ang = -M_PI * (double)(idx + 1) / (double)NVIEW - M_PI;
        float c = (float)cos(ang);
        float s = (float)sin(ang);
        if (fabsf(c) >= fabsf(s)) {          // row mode: stepped coord P = iy
            g_vp[idx] = make_float4(c, -s, s, c);
            g_vmode[idx] = 0;
        } else {                             // col mode: stepped coord P = ix
            g_vp[idx] = make_float4(-s, c, c, s);
            g_vmode[idx] = 1;
        }
    }

    if (idx < PADW * PADW) {
        int py = idx / PADW;
        int px = idx - py * PADW;
        int y = py - 1, xx = px - 1;
        float2 f = make_float2(0.f, 0.f);
        if (y >= 0 && y < IMG && xx >= 0 && xx < IMG) {
            f.x = x[y * IMG + xx];
            f.y = x[IMG * IMG + y * IMG + xx];
        }
        g_rowimg[py * PADW + px] = f;
        g_colimg[px * PADW + py] = f;
    }
}

__global__ __launch_bounds__(512) void fp_kernel() {
    __shared__ float2 srow[2][516];

    int v = blockIdx.x;            // view
    int q = blockIdx.y;            // row quarter
    int w = threadIdx.x;           // detector bin
    int r0 = q * RQ;

    float4 vp = g_vp[v];
    const float2* __restrict__ G = g_vmode[v] ? g_colimg : g_rowimg;

    float a  = vp.x;
    float bc = vp.y;
    float wr = (float)w - 255.5f;
    float A  = fmaf(vp.z, wr, 255.5f);
    float B  = fmaf(vp.w, wr, 255.5f);
    float inv_a = 1.0f / a;

    float acc0 = 0.f, acc1 = 0.f;

    // zero tail pads (never overwritten) + preload first row of this quarter
    if (w < 2) {
        srow[0][514 + w] = make_float2(0.f, 0.f);
        srow[1][514 + w] = make_float2(0.f, 0.f);
    }
    {
        const float2* src = G + (size_t)(r0 + 1) * PADW;
        srow[0][w] = src[w];
        if (w < 2) srow[0][512 + w] = src[512 + w];
    }

    for (int rr = 0; rr < RQ; rr++) {
        int r = r0 + rr;
        __syncthreads();
        if (rr + 1 < RQ) {
            const float2* src = G + (size_t)(r + 2) * PADW;
            int nb = (rr + 1) & 1;
            srow[nb][w] = src[w];
            if (w < 2) srow[nb][512 + w] = src[512 + w];
        }
        const float2* row = srow[rr & 1];

        float rf = (float)r;
        // h solving P(h)=r: hc = (r-A)/a + 255.5. Support |P-r|<1 spans < 2*sqrt(2);
        // 3 candidates from ceil(hc-1.4146) provably cover it.
        float hc = fmaf(rf - A, inv_a, 255.5f);
        float hb = ceilf(hc - 1.4146f);
        int   h0 = (int)hb;

        float hr0 = hb - 255.5f;
        float P = fmaf(a, hr0, A);
        float Q = fmaf(bc, hr0, B);

        #pragma unroll
        for (int k = 0; k < 3; k++) {
            float wp = 1.0f - fabsf(P - rf);
            wp = fmaxf(wp, 0.0f);
            if ((unsigned)(h0 + k) >= 512u) wp = 0.0f;   // branchless SEL

            float Qc = fminf(fmaxf(Q, -1.0f), 512.0f);   // clamp lands on zero pads
            float q0 = floorf(Qc);
            float wq = Qc - q0;
            int   px = (int)q0 + 1;                      // in [0, 513]

            float2 t0 = row[px];
            float2 t1 = row[px + 1];
            acc0 = fmaf(wp, fmaf(wq, t1.x - t0.x, t0.x), acc0);
            acc1 = fmaf(wp, fmaf(wq, t1.y - t0.y, t0.y), acc1);

            P += a;
            Q += bc;
        }
    }

    g_part[q][w * NVIEW + v]              = acc0;
    g_part[q][IMG * NVIEW + w * NVIEW + v] = acc1;
}

__global__ void combine_kernel(float* __restrict__ out) {
    int idx = blockIdx.x * blockDim.x + threadIdx.x;
    if (idx < OUTN) {
        float s = g_part[0][idx] + g_part[1][idx] + g_part[2][idx] + g_part[3][idx];
        out[idx] = s * 0.5f;
    }
}

extern "C" void kernel_launch(void* const* d_in, const int* in_sizes, int n_in,
                              void* d_out, int out_size) {
    const float* x = (const float*)d_in[0];
    float* out = (float*)d_out;

    int npix = PADW * PADW;
    prep_kernel<<<(npix + 255) / 256, 256>>>(x);

    dim3 grid(NVIEW, NQ);
    fp_kernel<<<grid, 512>>>();

    combine_kernel<<<(OUTN + 255) / 256, 256>>>(out);
}